// round 2
// baseline (speedup 1.0000x reference)
#include <cuda_runtime.h>
#include <math.h>

#define Bn 1024
#define Tn 512
#define KK 48
#define NEG (-10000.0f)
#define SSTART 46
#define SSTOP  47
#define BPB 8
#define NTHREADS (BPB * KK)   // 384

// Dynamic shared memory layout (bytes):
//   bp   : BPB*Tn*KK  uint8  = 196608
//   eav  : BPB*KK     float2 =   3072
//   trM  : KK*KK      float  =   9216
//   a0sh : BPB        float  =     32
//   msh  : BPB        float  =     32
//   gbuf : BPB*KK     float  =   1536
#define SMEM_BP    (BPB * Tn * KK)
#define SMEM_BYTES (SMEM_BP + BPB*KK*8 + KK*KK*4 + BPB*4 + BPB*4 + BPB*KK*4)

extern __shared__ unsigned char s_raw[];

__global__ void __launch_bounds__(NTHREADS, 1)
crf_fused_kernel(const float* __restrict__ feats,
                 const float* __restrict__ trans,
                 const int*   __restrict__ tags,
                 float*       __restrict__ out)
{
    unsigned char* bp  = s_raw;                                   // [BPB][Tn][KK]
    float2* eav        = (float2*)(s_raw + SMEM_BP);              // [BPB][KK] (exp(alpha-m), v)
    float*  trM        = (float*)(eav + BPB * KK);                // [KK*KK] masked transitions
    float*  a0sh       = trM + KK * KK;                           // [BPB]
    float*  msh        = a0sh + BPB;                              // [BPB]
    float*  gbuf       = msh + BPB;                               // [BPB*KK] gold partials

    const int tid = threadIdx.x;
    const int bl  = tid / KK;      // batch-in-block
    const int s   = tid % KK;      // owned next-state
    const int b   = blockIdx.x * BPB + bl;

    // Build masked transition matrix in shared (trans[next,prev]; mask row START, col STOP)
    for (int idx = tid; idx < KK * KK; idx += NTHREADS) {
        int n = idx / KK, p = idx % KK;
        float v = trans[idx];
        if (n == SSTART) v = NEG;
        if (p == SSTOP)  v = NEG;
        trM[idx] = v;
    }
    __syncthreads();

    // Cache this thread's rows in registers
    float Erow[KK], Trow[KK];
#pragma unroll
    for (int i = 0; i < KK; i++) {
        float tv = trM[s * KK + i];
        Trow[i] = tv;
        Erow[i] = __expf(tv);      // exp(-10000) underflows to exactly 0
    }
    const float tstop = trM[SSTOP * KK + s];

    // Gold score partials (strided over t)
    const float* fb = feats + (size_t)b * Tn * KK;
    const int*   tb = tags  + (size_t)b * Tn;
    {
        float gp = 0.0f;
        for (int t = s; t < Tn; t += KK) {
            int tg = tb[t];
            int pv = (t == 0) ? SSTART : tb[t - 1];
            gp += fb[(size_t)t * KK + tg] + trM[tg * KK + pv];
        }
        gbuf[bl * KK + s] = gp;
    }

    // Init: alpha = NEG except START=0 (so exp(alpha-0): START->1, else exp(-10000)=0)
    //       v     = NEG except START=0
    eav[bl * KK + s] = make_float2(s == SSTART ? 1.0f : 0.0f,
                                   s == SSTART ? 0.0f : NEG);
    if (s == 0) msh[bl] = 0.0f;

    float alpha = 0.0f, v = 0.0f;
    const float* fptr = fb + s;

#pragma unroll 1
    for (int t = 0; t < Tn; t++) {
        __syncthreads();
        const float m    = msh[bl];
        const float emit = *fptr;  fptr += KK;

        // 4 contiguous chains of 12 (contiguity preserves first-index argmax tie-break)
        float ss0 = 0.f, ss1 = 0.f, ss2 = 0.f, ss3 = 0.f;
        float bst0 = -INFINITY, bst1 = -INFINITY, bst2 = -INFINITY, bst3 = -INFINITY;
        int   bi0 = 0, bi1 = 12, bi2 = 24, bi3 = 36;
        const float2* ev = eav + bl * KK;
#pragma unroll
        for (int j = 0; j < 12; j++) {
            {
                float2 e = ev[j];
                ss0 += Erow[j] * e.x;
                float sc = e.y + Trow[j];
                if (sc > bst0) { bst0 = sc; bi0 = j; }
            }
            {
                float2 e = ev[12 + j];
                ss1 += Erow[12 + j] * e.x;
                float sc = e.y + Trow[12 + j];
                if (sc > bst1) { bst1 = sc; bi1 = 12 + j; }
            }
            {
                float2 e = ev[24 + j];
                ss2 += Erow[24 + j] * e.x;
                float sc = e.y + Trow[24 + j];
                if (sc > bst2) { bst2 = sc; bi2 = 24 + j; }
            }
            {
                float2 e = ev[36 + j];
                ss3 += Erow[36 + j] * e.x;
                float sc = e.y + Trow[36 + j];
                if (sc > bst3) { bst3 = sc; bi3 = 36 + j; }
            }
        }
        // In-order merge: keeps global first-occurrence argmax on exact ties
        float best = bst0; int bi = bi0;
        if (bst1 > best) { best = bst1; bi = bi1; }
        if (bst2 > best) { best = bst2; bi = bi2; }
        if (bst3 > best) { best = bst3; bi = bi3; }
        const float ssum = (ss0 + ss1) + (ss2 + ss3);

        alpha = emit + m + __logf(ssum);   // log(0) -> -inf for START row: correct
        v     = best + emit;               // bit-identical to reference ops

        bp[(bl * Tn + t) * KK + s] = (unsigned char)bi;
        if (s == 0) a0sh[bl] = alpha;
        __syncthreads();
        const float m2 = a0sh[bl];
        eav[bl * KK + s] = make_float2(__expf(alpha - m2), v);
        if (s == 0) msh[bl] = m2;
    }

    __syncthreads();
    // Terminal terms
    eav[bl * KK + s] = make_float2(alpha + tstop, v + tstop);
    __syncthreads();

    if (s == 0) {
        // gold reduce
        float gold = 0.0f;
        for (int i = 0; i < KK; i++) gold += gbuf[bl * KK + i];
        gold += trM[SSTOP * KK + tb[Tn - 1]];

        // logZ = LSE(termZ), best_last = first-argmax(termV)
        float mz = -INFINITY, bv = -INFINITY;
        int best_last = 0;
        for (int i = 0; i < KK; i++) {
            float2 e = eav[bl * KK + i];
            if (e.x > mz) mz = e.x;
            if (e.y > bv) { bv = e.y; best_last = i; }
        }
        float sz = 0.0f;
        for (int i = 0; i < KK; i++)
            sz += __expf(eav[bl * KK + i].x - mz);
        float logZ = mz + __logf(sz);

        out[b]      = logZ - gold;   // nll
        out[Bn + b] = bv;            // path_score

        // Backtrace from shared-memory backpointers
        int tag = best_last;
        const unsigned char* bpb = bp + (size_t)bl * Tn * KK;
        float* pout = out + 2 * Bn + (size_t)b * Tn;
        for (int t = Tn - 1; t >= 0; t--) {
            pout[t] = (float)tag;
            tag = bpb[t * KK + tag];
        }
    }
}

extern "C" void kernel_launch(void* const* d_in, const int* in_sizes, int n_in,
                              void* d_out, int out_size)
{
    const float* feats = (const float*)d_in[0];
    const float* trans = (const float*)d_in[1];
    const int*   tags  = (const int*)d_in[2];
    float* out = (float*)d_out;

    cudaFuncSetAttribute(crf_fused_kernel,
                         cudaFuncAttributeMaxDynamicSharedMemorySize, SMEM_BYTES);
    crf_fused_kernel<<<Bn / BPB, NTHREADS, SMEM_BYTES>>>(feats, trans, tags, out);
}